// round 14
// baseline (speedup 1.0000x reference)
#include <cuda_runtime.h>
#include <cuda_fp16.h>
#include <cstdint>
#include <math.h>

#define Bdim 128
#define Tdim 32
#define Edim 512
#define Hdim 1024
#define G4   4096
#define Vdim 32000
#define GRID 144
#define LDSS 36    // gemm_f16 SMEM row stride (words)
#define RWPAD 180  // recurrence SMEM row stride (words)

// ---------------- device scratch ----------------
__device__ __align__(16) __half g_Xh[Bdim * Tdim * Edim];          // 4 MB
__device__ __align__(16) float  g_G0[Bdim * Tdim * G4];            // 64 MB
__device__ __align__(16) __half g_ysh[Bdim * Tdim * Hdim];         // 8 MB
__device__ __align__(16) float  g_bias1[G4];
__device__ __align__(16) __half g_hcath[2][Tdim * 2048];           // [par][t][h0|h1]
__device__ __align__(16) float  g_c0[Tdim * Hdim];
__device__ __align__(16) float  g_c1[Tdim * Hdim];
__device__ __align__(16) __half g_W0h[(size_t)G4 * 1024];          // fp16(W_hh0) 8MB
__device__ __align__(16) __half g_W1h[(size_t)G4 * 2048];          // fp16([Wih1|Whh1]) 16MB
__device__ __align__(16) __half g_Wih0h[(size_t)G4 * 512];         // fp16(W_ih0) 4MB
__device__ __align__(16) __half g_fcWh[(size_t)Vdim * 1024];       // fp16(fc_W) 64MB
__device__ __align__(16) float  g_part0[3 * Tdim * G4];            // 1.5MB
__device__ __align__(16) float  g_part1[6 * Tdim * G4];            // 3MB
__device__ int g_cnt[2][16];
__device__ unsigned g_bar;
__device__ unsigned g_phase;

// ---------------- helpers ----------------
__device__ __forceinline__ uint32_t pack2(float a, float b) {
    __half2 h = __floats2half2_rn(a, b);
    return *reinterpret_cast<uint32_t*>(&h);
}

__device__ __forceinline__ void mma_f16(float c[4], const uint32_t a[4], const uint32_t b[2]) {
    asm volatile(
        "mma.sync.aligned.m16n8k16.row.col.f32.f16.f16.f32 "
        "{%0,%1,%2,%3}, {%4,%5,%6,%7}, {%8,%9}, {%0,%1,%2,%3};"
        : "+f"(c[0]), "+f"(c[1]), "+f"(c[2]), "+f"(c[3])
        : "r"(a[0]), "r"(a[1]), "r"(a[2]), "r"(a[3]), "r"(b[0]), "r"(b[1]));
}

__device__ __forceinline__ void cp16(void* s, const void* g) {
    uint32_t sa = (uint32_t)__cvta_generic_to_shared(s);
    asm volatile("cp.async.cg.shared.global [%0], [%1], 16;" :: "r"(sa), "l"(g));
}
__device__ __forceinline__ void cp_commit() { asm volatile("cp.async.commit_group;" ::: "memory"); }

__device__ __forceinline__ float sigm(float x) { return 1.f / (1.f + expf(-x)); }

__device__ __forceinline__ unsigned ldcg_u32(const unsigned* p) {
    unsigned v;
    asm volatile("ld.global.cg.u32 %0, [%1];" : "=r"(v) : "l"(p));
    return v;
}

// grid barrier
__device__ __forceinline__ void grid_bar(unsigned* local_phase) {
    __syncthreads();
    unsigned target = ++(*local_phase);
    if (threadIdx.x == 0) {
        __threadfence();
        unsigned old = atomicAdd(&g_bar, 1);
        if (old == GRID - 1) {
            atomicExch(&g_bar, 0);
            atomicAdd(&g_phase, 1);
        } else {
            while (ldcg_u32(&g_phase) < target) { __nanosleep(40); }
        }
        __threadfence();
    }
    __syncthreads();
}

// ---------------- init ----------------
__global__ void init_kernel(const float* __restrict__ b_ih1, const float* __restrict__ b_hh1) {
    int i = blockIdx.x * blockDim.x + threadIdx.x;
    if (i < Tdim * 2048) {
        g_hcath[0][i] = __float2half(0.f);
        g_hcath[1][i] = __float2half(0.f);
    }
    if (i < Tdim * Hdim) { g_c0[i] = 0.f; g_c1[i] = 0.f; }
    if (i < G4) g_bias1[i] = b_ih1[i] + b_hh1[i];
    if (i < 16) { g_cnt[0][i] = 0; g_cnt[1][i] = 0; }
    if (i == 0) { g_bar = 0; g_phase = 0; }
}

// generic fp32 -> fp16 convert (8 elements/thread)
__global__ void f2h(const float* __restrict__ src, __half* __restrict__ dst) {
    size_t i = ((size_t)blockIdx.x * blockDim.x + threadIdx.x) * 8;
    float4 v0 = *reinterpret_cast<const float4*>(src + i);
    float4 v1 = *reinterpret_cast<const float4*>(src + i + 4);
    uint4 h;
    h.x = pack2(v0.x, v0.y); h.y = pack2(v0.z, v0.w);
    h.z = pack2(v1.x, v1.y); h.w = pack2(v1.z, v1.w);
    *reinterpret_cast<uint4*>(dst + i) = h;
}

// g_W1h = fp16([W_ih1 | W_hh1]) : [4096][2048]
__global__ void make_w1cat(const float* __restrict__ Wi1, const float* __restrict__ Wh1) {
    size_t i = (size_t)blockIdx.x * 256 + threadIdx.x;   // float4 index; 2M total
    int n = (int)(i >> 9);
    int c4 = (int)(i & 511);
    const float4* src = (c4 < 256)
        ? reinterpret_cast<const float4*>(Wi1 + (size_t)n * Hdim) + c4
        : reinterpret_cast<const float4*>(Wh1 + (size_t)n * Hdim) + (c4 - 256);
    float4 v = *src;
    uint2 h;
    h.x = pack2(v.x, v.y); h.y = pack2(v.z, v.w);
    *reinterpret_cast<uint2*>(g_W1h + i * 4) = h;
}

// ---------------- build X (fp16) ----------------
__global__ void build_x(const float* __restrict__ features, const int* __restrict__ captions,
                        const float* __restrict__ embW) {
    int b = blockIdx.x, t = blockIdx.y;
    const float* src = (t == 0) ? (features + (size_t)b * Edim)
                                : (embW + (size_t)captions[b * Tdim + t] * Edim);
    float4 v = reinterpret_cast<const float4*>(src)[threadIdx.x];
    uint2 h;
    h.x = pack2(v.x, v.y); h.y = pack2(v.z, v.w);
    reinterpret_cast<uint2*>(g_Xh + ((size_t)b * Tdim + t) * Edim)[threadIdx.x] = h;
}

// ---------------- big fp16 GEMM: C[M,N] = A[M,K] @ W[N,K]^T + bias ----------------
// 512 threads, 16 warps (4/SMSP), warp tile 32x64. Same block tile + traffic as before.
#define BM 128
#define BN 256

__global__ void __launch_bounds__(512, 1) gemm_f16(
    const __half* __restrict__ A, const __half* __restrict__ W,
    const float* __restrict__ bias0, const float* __restrict__ bias1,
    float* __restrict__ C, int M, int N, int K)
{
    extern __shared__ uint32_t smw[];
    uint32_t* As = smw;                    // [2][BM][36] words
    uint32_t* Bs = smw + 2 * BM * LDSS;    // [2][BN][36] words

    int tid = threadIdx.x;
    int lane = tid & 31, warp = tid >> 5;
    int m0 = blockIdx.x * BM, n0 = blockIdx.y * BN;
    int wm = (warp >> 2) * 32, wn = (warp & 3) * 64;

    float acc[2][8][4];
    #pragma unroll
    for (int a = 0; a < 2; a++)
        #pragma unroll
        for (int b = 0; b < 8; b++)
            #pragma unroll
            for (int c = 0; c < 4; c++) acc[a][b][c] = 0.f;

    auto load_stage = [&](int s, int buf) {
        int k0 = s * 64;   // halves
        const __half* Ag = A + (size_t)m0 * K + k0;
        #pragma unroll
        for (int i = 0; i < 2; i++) {
            int idx = tid + i * 512;
            int m = idx >> 3, seg = idx & 7;
            cp16(&As[(buf * BM + m) * LDSS + seg * 4], Ag + (size_t)m * K + seg * 8);
        }
        const __half* Wg = W + (size_t)n0 * K + k0;
        #pragma unroll
        for (int i = 0; i < 4; i++) {
            int idx = tid + i * 512;
            int n = idx >> 3, seg = idx & 7;
            cp16(&Bs[(buf * BN + n) * LDSS + seg * 4], Wg + (size_t)n * K + seg * 8);
        }
        cp_commit();
    };

    int S = K / 64;
    load_stage(0, 0);
    for (int s = 0; s < S; s++) {
        int buf = s & 1;
        if (s + 1 < S) {
            load_stage(s + 1, buf ^ 1);
            asm volatile("cp.async.wait_group 1;" ::: "memory");
        } else {
            asm volatile("cp.async.wait_group 0;" ::: "memory");
        }
        __syncthreads();
        const uint32_t* Ab = &As[buf * BM * LDSS];
        const uint32_t* Bb = &Bs[buf * BN * LDSS];
        #pragma unroll
        for (int kc = 0; kc < 4; kc++) {   // each kc = 16 halves = 8 words
            int c0 = kc * 8 + (lane & 3);
            uint32_t af[2][4];
            #pragma unroll
            for (int mt = 0; mt < 2; mt++) {
                int r = wm + mt * 16 + (lane >> 2);
                af[mt][0] = Ab[r * LDSS + c0];
                af[mt][1] = Ab[(r + 8) * LDSS + c0];
                af[mt][2] = Ab[r * LDSS + c0 + 4];
                af[mt][3] = Ab[(r + 8) * LDSS + c0 + 4];
            }
            #pragma unroll
            for (int nt = 0; nt < 8; nt++) {
                int n = wn + nt * 8 + (lane >> 2);
                uint32_t bf[2] = { Bb[n * LDSS + c0], Bb[n * LDSS + c0 + 4] };
                #pragma unroll
                for (int mt = 0; mt < 2; mt++) mma_f16(acc[mt][nt], af[mt], bf);
            }
        }
        __syncthreads();
    }

    #pragma unroll
    for (int nt = 0; nt < 8; nt++) {
        int col = n0 + wn + nt * 8 + 2 * (lane & 3);
        float bv0 = bias0[col], bv1 = bias0[col + 1];
        if (bias1) { bv0 += bias1[col]; bv1 += bias1[col + 1]; }
        #pragma unroll
        for (int mt = 0; mt < 2; mt++) {
            int row = m0 + wm + mt * 16 + (lane >> 2);
            float2 v;
            v.x = acc[mt][nt][0] + bv0; v.y = acc[mt][nt][1] + bv1;
            *reinterpret_cast<float2*>(C + (size_t)row * N + col) = v;
            v.x = acc[mt][nt][2] + bv0; v.y = acc[mt][nt][3] + bv1;
            *reinterpret_cast<float2*>(C + (size_t)(row + 8) * N + col) = v;
        }
    }
}

// ---------------- persistent recurrence kernel: weights SMEM-resident ----------------
// 144 blocks (1/SM), 512 threads = 16 warps. (round-12 proven version)
// Blocks 0..47  : layer0  jt = b/3, ks = b%3  (K=1024: widths 352/336/336)
// Blocks 48..143: layer1  jt = lb/6, ks = lb%6 (K=2048: widths 352,352,336x4)
__global__ void __launch_bounds__(512, 1) recurrence_kernel()
{
    extern __shared__ uint32_t smw[];
    uint32_t* Ws = smw;                  // [256][RWPAD] words
    uint32_t* As = smw + 256 * RWPAD;    // [32][RWPAD] words

    int bid = blockIdx.x;
    int tid = threadIdx.x, lane = tid & 31, warp = tid >> 5;
    int layer = (bid >= 48) ? 1 : 0;
    int jt, ks, KS, cstart, cw;
    if (!layer) {
        jt = bid / 3; ks = bid % 3; KS = 3;
        cstart = (ks == 0) ? 0 : 352 + (ks - 1) * 336;
        cw = (ks == 0) ? 352 : 336;
    } else {
        int lb = bid - 48;
        jt = lb / 6; ks = lb % 6; KS = 6;
        cstart = (ks < 2) ? ks * 352 : 704 + (ks - 2) * 336;
        cw = (ks < 2) ? 352 : 336;
    }
    const __half* W = layer ? g_W1h : g_W0h;
    int wstride = layer ? 2048 : 1024;     // halves
    float* gpart = layer ? g_part1 : g_part0;
    int cw8 = cw >> 3;     // 16B chunks per row
    int kcnt = cw >> 4;    // k-groups of 16 halves

    // ---- one-time weight slice load ----
    for (int idx = tid; idx < 256 * cw8; idx += 512) {
        int wr = idx / cw8, seg = idx - wr * cw8;
        int grow = (wr >> 6) * 1024 + jt * 64 + (wr & 63);
        cp16(&Ws[wr * RWPAD + seg * 4], W + (size_t)grow * wstride + cstart + seg * 8);
    }
    cp_commit();
    asm volatile("cp.async.wait_group 0;" ::: "memory");
    __syncthreads();

    unsigned local_phase = 0;
    __shared__ int doEpi;

    for (int s = 0; s <= Bdim; s++) {
        int par = s & 1;
        bool active = layer ? (s >= 1) : (s < Bdim);

        if (active) {
            const __half* A = g_hcath[par];

            // load A slice [32][cw]
            for (int idx = tid; idx < 32 * cw8; idx += 512) {
                int row = idx / cw8, seg = idx - row * cw8;
                cp16(&As[row * RWPAD + seg * 4], A + row * 2048 + cstart + seg * 8);
            }
            cp_commit();
            asm volatile("cp.async.wait_group 0;" ::: "memory");
            __syncthreads();

            float acc[2][2][4];
            #pragma unroll
            for (int nt = 0; nt < 2; nt++)
                #pragma unroll
                for (int m = 0; m < 2; m++)
                    #pragma unroll
                    for (int c = 0; c < 4; c++) acc[nt][m][c] = 0.f;

            int r = lane >> 2;
            for (int kc = 0; kc < kcnt; kc++) {
                int c0 = kc * 8 + (lane & 3);
                uint32_t af[2][4];
                #pragma unroll
                for (int m = 0; m < 2; m++) {
                    af[m][0] = As[(m * 16 + r) * RWPAD + c0];
                    af[m][1] = As[(m * 16 + r + 8) * RWPAD + c0];
                    af[m][2] = As[(m * 16 + r) * RWPAD + c0 + 4];
                    af[m][3] = As[(m * 16 + r + 8) * RWPAD + c0 + 4];
                }
                #pragma unroll
                for (int nt = 0; nt < 2; nt++) {
                    int srow = warp * 16 + nt * 8 + r;
                    uint32_t bf[2] = { Ws[srow * RWPAD + c0], Ws[srow * RWPAD + c0 + 4] };
                    mma_f16(acc[nt][0], af[0], bf);
                    mma_f16(acc[nt][1], af[1], bf);
                }
            }

            // store partials to fixed slots
            #pragma unroll
            for (int nt = 0; nt < 2; nt++) {
                int col = (warp >> 2) * 1024 + jt * 64 + (warp & 3) * 16 + nt * 8 + 2 * (lane & 3);
                #pragma unroll
                for (int m = 0; m < 2; m++) {
                    int row = m * 16 + (lane >> 2);
                    *reinterpret_cast<float2*>(gpart + ((size_t)(ks * 32 + row) * G4 + col)) =
                        make_float2(acc[nt][m][0], acc[nt][m][1]);
                    *reinterpret_cast<float2*>(gpart + ((size_t)(ks * 32 + row + 8) * G4 + col)) =
                        make_float2(acc[nt][m][2], acc[nt][m][3]);
                }
            }
            __threadfence();
            __syncthreads();
            if (tid == 0) {
                int old = atomicAdd(&g_cnt[layer][jt], 1);
                doEpi = (old == KS - 1) ? 1 : 0;
                if (doEpi) atomicExch(&g_cnt[layer][jt], 0);
            }
            __syncthreads();

            if (doEpi) {
                __threadfence();   // acquire other blocks' partials
                __half* hout = g_hcath[par ^ 1];
                if (!layer) {
                    #pragma unroll
                    for (int i = 0; i < 4; i++) {
                        int idx = tid + i * 512;
                        int t = idx >> 6, j = jt * 64 + (idx & 63);
                        float sg[4];
                        #pragma unroll
                        for (int g = 0; g < 4; g++) {
                            float ssum = g_G0[((size_t)s * 32 + t) * G4 + g * 1024 + j];
                            #pragma unroll
                            for (int k = 0; k < 3; k++)
                                ssum += __ldcg(g_part0 + ((size_t)(k * 32 + t) * G4 + g * 1024 + j));
                            sg[g] = ssum;
                        }
                        float cn = sigm(sg[1]) * g_c0[t * Hdim + j] + sigm(sg[0]) * tanhf(sg[2]);
                        float hn = sigm(sg[3]) * tanhf(cn);
                        g_c0[t * Hdim + j] = cn;
                        hout[t * 2048 + j] = __float2half(hn);
                    }
                } else {
                    #pragma unroll
                    for (int i = 0; i < 4; i++) {
                        int idx = tid + i * 512;
                        int t = idx >> 6, j = jt * 64 + (idx & 63);
                        float sg[4];
                        #pragma unroll
                        for (int g = 0; g < 4; g++) {
                            float ssum = g_bias1[g * 1024 + j];
                            #pragma unroll
                            for (int k = 0; k < 6; k++)
                                ssum += __ldcg(g_part1 + ((size_t)(k * 32 + t) * G4 + g * 1024 + j));
                            sg[g] = ssum;
                        }
                        float cn = sigm(sg[1]) * g_c1[t * Hdim + j] + sigm(sg[0]) * tanhf(sg[2]);
                        float hn = sigm(sg[3]) * tanhf(cn);
                        g_c1[t * Hdim + j] = cn;
                        __half hr = __float2half(hn);
                        hout[t * 2048 + 1024 + j] = hr;
                        g_ysh[((size_t)(s - 1) * 32 + t) * Hdim + j] = hr;
                    }
                }
            }
        }

        grid_bar(&local_phase);
    }
}

// ---------------- launch ----------------
extern "C" void kernel_launch(void* const* d_in, const int* in_sizes, int n_in,
                              void* d_out, int out_size)
{
    const float* features = (const float*)d_in[0];
    const int*   captions = (const int*)d_in[1];
    const float* embed_W  = (const float*)d_in[2];
    const float* W_ih0    = (const float*)d_in[3];
    const float* W_hh0    = (const float*)d_in[4];
    const float* b_ih0    = (const float*)d_in[5];
    const float* b_hh0    = (const float*)d_in[6];
    const float* W_ih1    = (const float*)d_in[7];
    const float* W_hh1    = (const float*)d_in[8];
    const float* b_ih1    = (const float*)d_in[9];
    const float* b_hh1    = (const float*)d_in[10];
    const float* fc_W     = (const float*)d_in[11];
    const float* fc_b     = (const float*)d_in[12];
    float* out = (float*)d_out;

    void *pXh = nullptr, *pG0 = nullptr, *pysh = nullptr;
    void *pW0h = nullptr, *pWih0h = nullptr, *pfcWh = nullptr;
    cudaGetSymbolAddress(&pXh, g_Xh);
    cudaGetSymbolAddress(&pG0, g_G0);
    cudaGetSymbolAddress(&pysh, g_ysh);
    cudaGetSymbolAddress(&pW0h, g_W0h);
    cudaGetSymbolAddress(&pWih0h, g_Wih0h);
    cudaGetSymbolAddress(&pfcWh, g_fcWh);

    size_t smem_gemm = (size_t)(2 * (BM + BN) * LDSS) * sizeof(uint32_t);   // ~108 KB
    cudaFuncSetAttribute(gemm_f16, cudaFuncAttributeMaxDynamicSharedMemorySize, (int)smem_gemm);
    size_t smem_rec = (size_t)((256 + 32) * RWPAD) * sizeof(uint32_t);      // 207,360 B
    cudaFuncSetAttribute(recurrence_kernel, cudaFuncAttributeMaxDynamicSharedMemorySize, (int)smem_rec);

    init_kernel<<<(Tdim * 2048 + 255) / 256, 256>>>(b_ih1, b_hh1);
    f2h<<<2048, 256>>>(W_hh0, (__half*)pW0h);            // 4M elems
    f2h<<<1024, 256>>>(W_ih0, (__half*)pWih0h);          // 2M elems
    f2h<<<16000, 256>>>(fc_W, (__half*)pfcWh);           // 32.77M elems
    make_w1cat<<<8192, 256>>>(W_ih1, W_hh1);
    build_x<<<dim3(Bdim, Tdim), 128>>>(features, captions, embed_W);

    // G0 = X @ W_ih0^T + b_ih0 + b_hh0   (M=4096, N=4096, K=512)
    gemm_f16<<<dim3(G4 / BM, G4 / BN), 512, smem_gemm>>>(
        (const __half*)pXh, (const __half*)pWih0h, b_ih0, b_hh0,
        (float*)pG0, Bdim * Tdim, G4, Edim);

    // persistent recurrence: all 129 fused steps, weights SMEM-resident
    recurrence_kernel<<<GRID, 512, smem_rec>>>();

    // logits = ys @ fc_W^T + fc_b   (M=4096, N=32000, K=1024)
    gemm_f16<<<dim3((Bdim * Tdim) / BM, Vdim / BN), 512, smem_gemm>>>(
        (const __half*)pysh, (const __half*)pfcWh, fc_b, nullptr,
        out, Bdim * Tdim, Vdim, Hdim);
}

// round 15
// speedup vs baseline: 1.1035x; 1.1035x over previous
#include <cuda_runtime.h>
#include <cuda_fp16.h>
#include <cstdint>
#include <math.h>

#define Bdim 128
#define Tdim 32
#define Edim 512
#define Hdim 1024
#define G4   4096
#define Vdim 32000
#define GRID 144
#define LDSS 36    // gemm_f16 SMEM row stride (words)
#define RWPAD 180  // recurrence SMEM row stride (words)

// ---------------- device scratch ----------------
__device__ __align__(16) __half g_Xh[Bdim * Tdim * Edim];          // 4 MB
__device__ __align__(16) float  g_G0[Bdim * Tdim * G4];            // 64 MB
__device__ __align__(16) __half g_ysh[Bdim * Tdim * Hdim];         // 8 MB
__device__ __align__(16) float  g_bias1[G4];
__device__ __align__(16) __half g_hcat4[4][Tdim * 2048];           // 4-deep [t][h0|h1]
__device__ __align__(16) float  g_c0[Tdim * Hdim];
__device__ __align__(16) float  g_c1[Tdim * Hdim];
__device__ __align__(16) __half g_W0h[(size_t)G4 * 1024];          // fp16(W_hh0) 8MB
__device__ __align__(16) __half g_W1h[(size_t)G4 * 2048];          // fp16([Wih1|Whh1]) 16MB
__device__ __align__(16) __half g_Wih0h[(size_t)G4 * 512];         // fp16(W_ih0) 4MB
__device__ __align__(16) __half g_fcWh[(size_t)Vdim * 1024];       // fp16(fc_W) 64MB
__device__ __align__(16) float  g_part0[3 * Tdim * G4];            // 1.5MB
__device__ __align__(16) float  g_part1[6 * Tdim * G4];            // 3MB
__device__ unsigned g_hready0, g_h1ready;
__device__ unsigned g_tc0[16], g_tc1[16];

// ---------------- helpers ----------------
__device__ __forceinline__ uint32_t pack2(float a, float b) {
    __half2 h = __floats2half2_rn(a, b);
    return *reinterpret_cast<uint32_t*>(&h);
}

__device__ __forceinline__ void mma_f16(float c[4], const uint32_t a[4], const uint32_t b[2]) {
    asm volatile(
        "mma.sync.aligned.m16n8k16.row.col.f32.f16.f16.f32 "
        "{%0,%1,%2,%3}, {%4,%5,%6,%7}, {%8,%9}, {%0,%1,%2,%3};"
        : "+f"(c[0]), "+f"(c[1]), "+f"(c[2]), "+f"(c[3])
        : "r"(a[0]), "r"(a[1]), "r"(a[2]), "r"(a[3]), "r"(b[0]), "r"(b[1]));
}

__device__ __forceinline__ void cp16(void* s, const void* g) {
    uint32_t sa = (uint32_t)__cvta_generic_to_shared(s);
    asm volatile("cp.async.cg.shared.global [%0], [%1], 16;" :: "r"(sa), "l"(g));
}
__device__ __forceinline__ void cp_commit() { asm volatile("cp.async.commit_group;" ::: "memory"); }

__device__ __forceinline__ float sigm(float x) { return 1.f / (1.f + expf(-x)); }

__device__ __forceinline__ unsigned ldcg_u32(const unsigned* p) {
    unsigned v;
    asm volatile("ld.global.cg.u32 %0, [%1];" : "=r"(v) : "l"(p));
    return v;
}

__device__ __forceinline__ void spin_ge(const unsigned* c, unsigned t) {
    while (ldcg_u32(c) < t) { __nanosleep(20); }
}

// ---------------- init ----------------
__global__ void init_kernel(const float* __restrict__ b_ih1, const float* __restrict__ b_hh1) {
    int i = blockIdx.x * blockDim.x + threadIdx.x;
    if (i < 4 * Tdim * 2048) reinterpret_cast<__half*>(g_hcat4)[i] = __float2half(0.f);
    if (i < Tdim * Hdim) { g_c0[i] = 0.f; g_c1[i] = 0.f; }
    if (i < G4) g_bias1[i] = b_ih1[i] + b_hh1[i];
    if (i < 16) { g_tc0[i] = 0u; g_tc1[i] = 0u; }
    if (i == 0) { g_hready0 = 0u; g_h1ready = 0u; }
}

// generic fp32 -> fp16 convert (8 elements/thread)
__global__ void f2h(const float* __restrict__ src, __half* __restrict__ dst) {
    size_t i = ((size_t)blockIdx.x * blockDim.x + threadIdx.x) * 8;
    float4 v0 = *reinterpret_cast<const float4*>(src + i);
    float4 v1 = *reinterpret_cast<const float4*>(src + i + 4);
    uint4 h;
    h.x = pack2(v0.x, v0.y); h.y = pack2(v0.z, v0.w);
    h.z = pack2(v1.x, v1.y); h.w = pack2(v1.z, v1.w);
    *reinterpret_cast<uint4*>(dst + i) = h;
}

// g_W1h = fp16([W_ih1 | W_hh1]) : [4096][2048]
__global__ void make_w1cat(const float* __restrict__ Wi1, const float* __restrict__ Wh1) {
    size_t i = (size_t)blockIdx.x * 256 + threadIdx.x;   // float4 index; 2M total
    int n = (int)(i >> 9);
    int c4 = (int)(i & 511);
    const float4* src = (c4 < 256)
        ? reinterpret_cast<const float4*>(Wi1 + (size_t)n * Hdim) + c4
        : reinterpret_cast<const float4*>(Wh1 + (size_t)n * Hdim) + (c4 - 256);
    float4 v = *src;
    uint2 h;
    h.x = pack2(v.x, v.y); h.y = pack2(v.z, v.w);
    *reinterpret_cast<uint2*>(g_W1h + i * 4) = h;
}

// ---------------- build X (fp16) ----------------
__global__ void build_x(const float* __restrict__ features, const int* __restrict__ captions,
                        const float* __restrict__ embW) {
    int b = blockIdx.x, t = blockIdx.y;
    const float* src = (t == 0) ? (features + (size_t)b * Edim)
                                : (embW + (size_t)captions[b * Tdim + t] * Edim);
    float4 v = reinterpret_cast<const float4*>(src)[threadIdx.x];
    uint2 h;
    h.x = pack2(v.x, v.y); h.y = pack2(v.z, v.w);
    reinterpret_cast<uint2*>(g_Xh + ((size_t)b * Tdim + t) * Edim)[threadIdx.x] = h;
}

// ---------------- big fp16 GEMM (round-12 proven, 256 threads) ----------------
#define BM 128
#define BN 256

__global__ void __launch_bounds__(256, 1) gemm_f16(
    const __half* __restrict__ A, const __half* __restrict__ W,
    const float* __restrict__ bias0, const float* __restrict__ bias1,
    float* __restrict__ C, int M, int N, int K)
{
    extern __shared__ uint32_t smw[];
    uint32_t* As = smw;                    // [2][BM][36] words
    uint32_t* Bs = smw + 2 * BM * LDSS;    // [2][BN][36] words

    int tid = threadIdx.x;
    int lane = tid & 31, warp = tid >> 5;
    int m0 = blockIdx.x * BM, n0 = blockIdx.y * BN;
    int wm = (warp >> 2) * 64, wn = (warp & 3) * 64;

    float acc[4][8][4];
    #pragma unroll
    for (int a = 0; a < 4; a++)
        #pragma unroll
        for (int b = 0; b < 8; b++)
            #pragma unroll
            for (int c = 0; c < 4; c++) acc[a][b][c] = 0.f;

    auto load_stage = [&](int s, int buf) {
        int k0 = s * 64;   // halves
        const __half* Ag = A + (size_t)m0 * K + k0;
        #pragma unroll
        for (int i = 0; i < 4; i++) {
            int idx = tid + i * 256;
            int m = idx >> 3, seg = idx & 7;
            cp16(&As[(buf * BM + m) * LDSS + seg * 4], Ag + (size_t)m * K + seg * 8);
        }
        const __half* Wg = W + (size_t)n0 * K + k0;
        #pragma unroll
        for (int i = 0; i < 8; i++) {
            int idx = tid + i * 256;
            int n = idx >> 3, seg = idx & 7;
            cp16(&Bs[(buf * BN + n) * LDSS + seg * 4], Wg + (size_t)n * K + seg * 8);
        }
        cp_commit();
    };

    int S = K / 64;
    load_stage(0, 0);
    for (int s = 0; s < S; s++) {
        int buf = s & 1;
        if (s + 1 < S) {
            load_stage(s + 1, buf ^ 1);
            asm volatile("cp.async.wait_group 1;" ::: "memory");
        } else {
            asm volatile("cp.async.wait_group 0;" ::: "memory");
        }
        __syncthreads();
        const uint32_t* Ab = &As[buf * BM * LDSS];
        const uint32_t* Bb = &Bs[buf * BN * LDSS];
        #pragma unroll
        for (int kc = 0; kc < 4; kc++) {   // each kc = 16 halves = 8 words
            int c0 = kc * 8 + (lane & 3);
            uint32_t af[4][4];
            #pragma unroll
            for (int mt = 0; mt < 4; mt++) {
                int r = wm + mt * 16 + (lane >> 2);
                af[mt][0] = Ab[r * LDSS + c0];
                af[mt][1] = Ab[(r + 8) * LDSS + c0];
                af[mt][2] = Ab[r * LDSS + c0 + 4];
                af[mt][3] = Ab[(r + 8) * LDSS + c0 + 4];
            }
            #pragma unroll
            for (int nt = 0; nt < 8; nt++) {
                int n = wn + nt * 8 + (lane >> 2);
                uint32_t bf[2] = { Bb[n * LDSS + c0], Bb[n * LDSS + c0 + 4] };
                #pragma unroll
                for (int mt = 0; mt < 4; mt++) mma_f16(acc[mt][nt], af[mt], bf);
            }
        }
        __syncthreads();
    }

    #pragma unroll
    for (int nt = 0; nt < 8; nt++) {
        int col = n0 + wn + nt * 8 + 2 * (lane & 3);
        float bv0 = bias0[col], bv1 = bias0[col + 1];
        if (bias1) { bv0 += bias1[col]; bv1 += bias1[col + 1]; }
        #pragma unroll
        for (int mt = 0; mt < 4; mt++) {
            int row = m0 + wm + mt * 16 + (lane >> 2);
            float2 v;
            v.x = acc[mt][nt][0] + bv0; v.y = acc[mt][nt][1] + bv1;
            *reinterpret_cast<float2*>(C + (size_t)row * N + col) = v;
            v.x = acc[mt][nt][2] + bv0; v.y = acc[mt][nt][3] + bv1;
            *reinterpret_cast<float2*>(C + (size_t)(row + 8) * N + col) = v;
        }
    }
}

// ---------------- persistent recurrence: dataflow sync, no global barrier ----------------
// 144 blocks (1/SM), 512 threads.
// Blocks 0..47  : layer0  jt = b/3, ks = b%3  (K=1024: widths 352/336/336), phases s=0..127
// Blocks 48..143: layer1  jt = lb/6, ks = lb%6 (K=2048: widths 352,352,336x4), phases s=1..128
// h state: 4-deep ping-pong g_hcat4[s&3]; phase s reads buf[(s-1)&3], writes buf[s&3].
// Sync: monotonic counters. hready0 += 1 per layer0 epilogue share (48/phase);
// h1ready += 1 per layer1 share (96/phase). Per-tile counters gate split epilogues.
__global__ void __launch_bounds__(512, 1) recurrence_kernel()
{
    extern __shared__ uint32_t smw[];
    uint32_t* Ws = smw;                  // [256][RWPAD] words
    uint32_t* As = smw + 256 * RWPAD;    // [32][RWPAD] words

    int bid = blockIdx.x;
    int tid = threadIdx.x, lane = tid & 31, warp = tid >> 5;
    int layer = (bid >= 48) ? 1 : 0;
    int jt, ks, KS, cstart, cw;
    if (!layer) {
        jt = bid / 3; ks = bid % 3; KS = 3;
        cstart = (ks == 0) ? 0 : 352 + (ks - 1) * 336;
        cw = (ks == 0) ? 352 : 336;
    } else {
        int lb = bid - 48;
        jt = lb / 6; ks = lb % 6; KS = 6;
        cstart = (ks < 2) ? ks * 352 : 704 + (ks - 2) * 336;
        cw = (ks < 2) ? 352 : 336;
    }
    const __half* W = layer ? g_W1h : g_W0h;
    int wstride = layer ? 2048 : 1024;     // halves
    float* gpart = layer ? g_part1 : g_part0;
    unsigned* tcp = layer ? &g_tc1[jt] : &g_tc0[jt];
    int cw8 = cw >> 3;     // 16B chunks per row
    int kcnt = cw >> 4;    // k-groups of 16 halves

    // epilogue row share (by ks): layer0 11/11/10; layer1 6,6,5,5,5,5
    int rs, rn;
    if (!layer) { rs = ks * 11; rn = (ks == 2) ? 10 : 11; }
    else        { rs = (ks < 2) ? ks * 6 : 12 + (ks - 2) * 5; rn = (ks < 2) ? 6 : 5; }

    // ---- one-time weight slice load ----
    for (int idx = tid; idx < 256 * cw8; idx += 512) {
        int wr = idx / cw8, seg = idx - wr * cw8;
        int grow = (wr >> 6) * 1024 + jt * 64 + (wr & 63);
        cp16(&Ws[wr * RWPAD + seg * 4], W + (size_t)grow * wstride + cstart + seg * 8);
    }
    cp_commit();
    asm volatile("cp.async.wait_group 0;" ::: "memory");
    __syncthreads();

    int sBeg = layer ? 1 : 0;
    int sEnd = layer ? 128 : 127;

    for (int s = sBeg; s <= sEnd; s++) {
        // ---- entry spin: inputs for this phase ----
        if (tid == 0) {
            if (!layer) {
                if (s >= 1) spin_ge(&g_hready0, 48u * (unsigned)s);
                if (s >= 3) spin_ge(&g_h1ready, 96u * (unsigned)(s - 2));
            } else {
                spin_ge(&g_hready0, 48u * (unsigned)s);
                if (s >= 2) spin_ge(&g_h1ready, 96u * (unsigned)(s - 1));
            }
            __threadfence();
        }
        __syncthreads();

        const __half* A = g_hcat4[(s - 1) & 3];

        // load A slice [32][cw]
        for (int idx = tid; idx < 32 * cw8; idx += 512) {
            int row = idx / cw8, seg = idx - row * cw8;
            cp16(&As[row * RWPAD + seg * 4], A + row * 2048 + cstart + seg * 8);
        }
        cp_commit();
        asm volatile("cp.async.wait_group 0;" ::: "memory");
        __syncthreads();

        float acc[2][2][4];
        #pragma unroll
        for (int nt = 0; nt < 2; nt++)
            #pragma unroll
            for (int m = 0; m < 2; m++)
                #pragma unroll
                for (int c = 0; c < 4; c++) acc[nt][m][c] = 0.f;

        int r = lane >> 2;
        for (int kc = 0; kc < kcnt; kc++) {
            int c0 = kc * 8 + (lane & 3);
            uint32_t af[2][4];
            #pragma unroll
            for (int m = 0; m < 2; m++) {
                af[m][0] = As[(m * 16 + r) * RWPAD + c0];
                af[m][1] = As[(m * 16 + r + 8) * RWPAD + c0];
                af[m][2] = As[(m * 16 + r) * RWPAD + c0 + 4];
                af[m][3] = As[(m * 16 + r + 8) * RWPAD + c0 + 4];
            }
            #pragma unroll
            for (int nt = 0; nt < 2; nt++) {
                int srow = warp * 16 + nt * 8 + r;
                uint32_t bf[2] = { Ws[srow * RWPAD + c0], Ws[srow * RWPAD + c0 + 4] };
                mma_f16(acc[nt][0], af[0], bf);
                mma_f16(acc[nt][1], af[1], bf);
            }
        }

        // store partials to fixed slots
        #pragma unroll
        for (int nt = 0; nt < 2; nt++) {
            int col = (warp >> 2) * 1024 + jt * 64 + (warp & 3) * 16 + nt * 8 + 2 * (lane & 3);
            #pragma unroll
            for (int m = 0; m < 2; m++) {
                int row = m * 16 + (lane >> 2);
                *reinterpret_cast<float2*>(gpart + ((size_t)(ks * 32 + row) * G4 + col)) =
                    make_float2(acc[nt][m][0], acc[nt][m][1]);
                *reinterpret_cast<float2*>(gpart + ((size_t)(ks * 32 + row + 8) * G4 + col)) =
                    make_float2(acc[nt][m][2], acc[nt][m][3]);
            }
        }
        __threadfence();
        __syncthreads();

        // ---- tile-group rendezvous (monotonic) ----
        unsigned tgt = layer ? 6u * (unsigned)s : 3u * (unsigned)(s + 1);
        if (tid == 0) {
            atomicAdd(tcp, 1u);
            spin_ge(tcp, tgt);
        }
        __syncthreads();
        __threadfence();   // acquire sibling partials

        // ---- split epilogue: this block handles rows [rs, rs+rn) of tile jt ----
        __half* hout = g_hcat4[s & 3];
        if (!layer) {
            for (int i = tid; i < rn * 64; i += 512) {
                int t = rs + (i >> 6), j = jt * 64 + (i & 63);
                float sg[4];
                #pragma unroll
                for (int g = 0; g < 4; g++) {
                    float ssum = g_G0[((size_t)s * 32 + t) * G4 + g * 1024 + j];
                    #pragma unroll
                    for (int k = 0; k < 3; k++)
                        ssum += __ldcg(g_part0 + ((size_t)(k * 32 + t) * G4 + g * 1024 + j));
                    sg[g] = ssum;
                }
                float cn = sigm(sg[1]) * g_c0[t * Hdim + j] + sigm(sg[0]) * tanhf(sg[2]);
                float hn = sigm(sg[3]) * tanhf(cn);
                g_c0[t * Hdim + j] = cn;
                hout[t * 2048 + j] = __float2half(hn);
            }
        } else {
            for (int i = tid; i < rn * 64; i += 512) {
                int t = rs + (i >> 6), j = jt * 64 + (i & 63);
                float sg[4];
                #pragma unroll
                for (int g = 0; g < 4; g++) {
                    float ssum = g_bias1[g * 1024 + j];
                    #pragma unroll
                    for (int k = 0; k < 6; k++)
                        ssum += __ldcg(g_part1 + ((size_t)(k * 32 + t) * G4 + g * 1024 + j));
                    sg[g] = ssum;
                }
                float cn = sigm(sg[1]) * g_c1[t * Hdim + j] + sigm(sg[0]) * tanhf(sg[2]);
                float hn = sigm(sg[3]) * tanhf(cn);
                g_c1[t * Hdim + j] = cn;
                __half hr = __float2half(hn);
                hout[t * 2048 + 1024 + j] = hr;
                g_ysh[((size_t)(s - 1) * 32 + t) * Hdim + j] = hr;
            }
        }
        __threadfence();
        __syncthreads();
        if (tid == 0) atomicAdd(layer ? &g_h1ready : &g_hready0, 1u);
    }
}

// ---------------- launch ----------------
extern "C" void kernel_launch(void* const* d_in, const int* in_sizes, int n_in,
                              void* d_out, int out_size)
{
    const float* features = (const float*)d_in[0];
    const int*   captions = (const int*)d_in[1];
    const float* embed_W  = (const float*)d_in[2];
    const float* W_ih0    = (const float*)d_in[3];
    const float* W_hh0    = (const float*)d_in[4];
    const float* b_ih0    = (const float*)d_in[5];
    const float* b_hh0    = (const float*)d_in[6];
    const float* W_ih1    = (const float*)d_in[7];
    const float* W_hh1    = (const float*)d_in[8];
    const float* b_ih1    = (const float*)d_in[9];
    const float* b_hh1    = (const float*)d_in[10];
    const float* fc_W     = (const float*)d_in[11];
    const float* fc_b     = (const float*)d_in[12];
    float* out = (float*)d_out;

    void *pXh = nullptr, *pG0 = nullptr, *pysh = nullptr;
    void *pW0h = nullptr, *pWih0h = nullptr, *pfcWh = nullptr;
    cudaGetSymbolAddress(&pXh, g_Xh);
    cudaGetSymbolAddress(&pG0, g_G0);
    cudaGetSymbolAddress(&pysh, g_ysh);
    cudaGetSymbolAddress(&pW0h, g_W0h);
    cudaGetSymbolAddress(&pWih0h, g_Wih0h);
    cudaGetSymbolAddress(&pfcWh, g_fcWh);

    size_t smem_gemm = (size_t)(2 * (BM + BN) * LDSS) * sizeof(uint32_t);   // ~108 KB
    cudaFuncSetAttribute(gemm_f16, cudaFuncAttributeMaxDynamicSharedMemorySize, (int)smem_gemm);
    size_t smem_rec = (size_t)((256 + 32) * RWPAD) * sizeof(uint32_t);      // 207,360 B
    cudaFuncSetAttribute(recurrence_kernel, cudaFuncAttributeMaxDynamicSharedMemorySize, (int)smem_rec);

    init_kernel<<<(4 * Tdim * 2048 + 255) / 256, 256>>>(b_ih1, b_hh1);
    f2h<<<2048, 256>>>(W_hh0, (__half*)pW0h);            // 4M elems
    f2h<<<1024, 256>>>(W_ih0, (__half*)pWih0h);          // 2M elems
    f2h<<<16000, 256>>>(fc_W, (__half*)pfcWh);           // 32.77M elems
    make_w1cat<<<8192, 256>>>(W_ih1, W_hh1);
    build_x<<<dim3(Bdim, Tdim), 128>>>(features, captions, embed_W);

    // G0 = X @ W_ih0^T + b_ih0 + b_hh0   (M=4096, N=4096, K=512)
    gemm_f16<<<dim3(G4 / BM, G4 / BN), 256, smem_gemm>>>(
        (const __half*)pXh, (const __half*)pWih0h, b_ih0, b_hh0,
        (float*)pG0, Bdim * Tdim, G4, Edim);

    // persistent recurrence: dataflow-synchronized, weights SMEM-resident
    recurrence_kernel<<<GRID, 512, smem_rec>>>();

    // logits = ys @ fc_W^T + fc_b   (M=4096, N=32000, K=1024)
    gemm_f16<<<dim3((Bdim * Tdim) / BM, Vdim / BN), 256, smem_gemm>>>(
        (const __half*)pysh, (const __half*)pfcWh, fc_b, nullptr,
        out, Bdim * Tdim, Vdim, Hdim);
}